// round 3
// baseline (speedup 1.0000x reference)
#include <cuda_runtime.h>

#define DIMC   256
#define NHEADS 8
#define HDIM   32
#define MAXN   10048

// Scratch (no cudaMalloc allowed) — ~41 MB of __device__ globals.
__device__ float g_q[MAXN * DIMC];
__device__ float g_k[MAXN * DIMC];
__device__ float g_v[MAXN * DIMC];
__device__ float g_acc[MAXN * DIMC];

// ---------------------------------------------------------------------------
// Zero the accumulator.
// ---------------------------------------------------------------------------
__global__ void __launch_bounds__(256) zero_acc_kernel(int n4) {
    int i = blockIdx.x * blockDim.x + threadIdx.x;
    float4 z = make_float4(0.f, 0.f, 0.f, 0.f);
    int stride = gridDim.x * blockDim.x;
    for (; i < n4; i += stride)
        reinterpret_cast<float4*>(g_acc)[i] = z;
}

// ---------------------------------------------------------------------------
// Tiled fp32 GEMM:  C[m][n] = sum_k X[m][k] * W[n][k] + bias[n]
// BM=BN=128, BK=16, 256 threads, 8x8 outputs/thread, double-buffered smem.
// ---------------------------------------------------------------------------
#define BM 128
#define BN 128
#define BK 16

__device__ __forceinline__ void gemm_tile(
    const float* __restrict__ X, int M,
    const float* __restrict__ W,
    const float* __restrict__ Bv,
    float* __restrict__ C,
    int m0, int n0)
{
    __shared__ float As[2][BK][BM];
    __shared__ float Bs[2][BK][BN];

    int tid = threadIdx.x;
    int tx = tid & 15;           // 0..15 -> output cols tx*8
    int ty = tid >> 4;           // 0..15 -> output rows ty*8
    int lrow = tid >> 2;         // 0..63
    int lk   = (tid & 3) << 2;   // 0,4,8,12

    bool av0 = (m0 + lrow) < M;
    bool av1 = (m0 + lrow + 64) < M;

    const float* Ap0 = X + (size_t)(m0 + lrow) * DIMC + lk;
    const float* Ap1 = X + (size_t)(m0 + lrow + 64) * DIMC + lk;
    const float* Bp0 = W + (size_t)(n0 + lrow) * DIMC + lk;
    const float* Bp1 = W + (size_t)(n0 + lrow + 64) * DIMC + lk;

    float acc[8][8];
#pragma unroll
    for (int i = 0; i < 8; i++)
#pragma unroll
        for (int j = 0; j < 8; j++) acc[i][j] = 0.f;

    const float4 zf4 = make_float4(0.f, 0.f, 0.f, 0.f);

    // Preload chunk 0.
    float4 ra0 = av0 ? *reinterpret_cast<const float4*>(Ap0) : zf4;
    float4 ra1 = av1 ? *reinterpret_cast<const float4*>(Ap1) : zf4;
    float4 rb0 = *reinterpret_cast<const float4*>(Bp0);
    float4 rb1 = *reinterpret_cast<const float4*>(Bp1);

    int buf = 0;
    {
        As[0][lk + 0][lrow] = ra0.x; As[0][lk + 1][lrow] = ra0.y;
        As[0][lk + 2][lrow] = ra0.z; As[0][lk + 3][lrow] = ra0.w;
        As[0][lk + 0][lrow + 64] = ra1.x; As[0][lk + 1][lrow + 64] = ra1.y;
        As[0][lk + 2][lrow + 64] = ra1.z; As[0][lk + 3][lrow + 64] = ra1.w;
        Bs[0][lk + 0][lrow] = rb0.x; Bs[0][lk + 1][lrow] = rb0.y;
        Bs[0][lk + 2][lrow] = rb0.z; Bs[0][lk + 3][lrow] = rb0.w;
        Bs[0][lk + 0][lrow + 64] = rb1.x; Bs[0][lk + 1][lrow + 64] = rb1.y;
        Bs[0][lk + 2][lrow + 64] = rb1.z; Bs[0][lk + 3][lrow + 64] = rb1.w;
    }
    __syncthreads();

    const int NK = DIMC / BK;   // 16
#pragma unroll 1
    for (int kc = 0; kc < NK; kc++) {
        // Prefetch next chunk from global into registers.
        if (kc + 1 < NK) {
            int ko = (kc + 1) * BK;
            ra0 = av0 ? *reinterpret_cast<const float4*>(Ap0 + ko) : zf4;
            ra1 = av1 ? *reinterpret_cast<const float4*>(Ap1 + ko) : zf4;
            rb0 = *reinterpret_cast<const float4*>(Bp0 + ko);
            rb1 = *reinterpret_cast<const float4*>(Bp1 + ko);
        }

        // Compute on current buffer.
#pragma unroll
        for (int kk = 0; kk < BK; kk++) {
            float4 a0 = *reinterpret_cast<const float4*>(&As[buf][kk][ty << 3]);
            float4 a1 = *reinterpret_cast<const float4*>(&As[buf][kk][(ty << 3) + 4]);
            float4 b0 = *reinterpret_cast<const float4*>(&Bs[buf][kk][tx << 3]);
            float4 b1 = *reinterpret_cast<const float4*>(&Bs[buf][kk][(tx << 3) + 4]);
            float ar[8] = {a0.x, a0.y, a0.z, a0.w, a1.x, a1.y, a1.z, a1.w};
            float br[8] = {b0.x, b0.y, b0.z, b0.w, b1.x, b1.y, b1.z, b1.w};
#pragma unroll
            for (int i = 0; i < 8; i++)
#pragma unroll
                for (int j = 0; j < 8; j++)
                    acc[i][j] = fmaf(ar[i], br[j], acc[i][j]);
        }

        if (kc + 1 < NK) {
            int nb = buf ^ 1;
            As[nb][lk + 0][lrow] = ra0.x; As[nb][lk + 1][lrow] = ra0.y;
            As[nb][lk + 2][lrow] = ra0.z; As[nb][lk + 3][lrow] = ra0.w;
            As[nb][lk + 0][lrow + 64] = ra1.x; As[nb][lk + 1][lrow + 64] = ra1.y;
            As[nb][lk + 2][lrow + 64] = ra1.z; As[nb][lk + 3][lrow + 64] = ra1.w;
            Bs[nb][lk + 0][lrow] = rb0.x; Bs[nb][lk + 1][lrow] = rb0.y;
            Bs[nb][lk + 2][lrow] = rb0.z; Bs[nb][lk + 3][lrow] = rb0.w;
            Bs[nb][lk + 0][lrow + 64] = rb1.x; Bs[nb][lk + 1][lrow + 64] = rb1.y;
            Bs[nb][lk + 2][lrow + 64] = rb1.z; Bs[nb][lk + 3][lrow + 64] = rb1.w;
            __syncthreads();
            buf = nb;
        }
    }

    // Epilogue: bias + store.
    float4 bb0 = *reinterpret_cast<const float4*>(Bv + n0 + (tx << 3));
    float4 bb1 = *reinterpret_cast<const float4*>(Bv + n0 + (tx << 3) + 4);
#pragma unroll
    for (int i = 0; i < 8; i++) {
        int gm = m0 + (ty << 3) + i;
        if (gm < M) {
            float* cp = C + (size_t)gm * DIMC + n0 + (tx << 3);
            float4 o0 = make_float4(acc[i][0] + bb0.x, acc[i][1] + bb0.y,
                                    acc[i][2] + bb0.z, acc[i][3] + bb0.w);
            float4 o1 = make_float4(acc[i][4] + bb1.x, acc[i][5] + bb1.y,
                                    acc[i][6] + bb1.z, acc[i][7] + bb1.w);
            *reinterpret_cast<float4*>(cp)     = o0;
            *reinterpret_cast<float4*>(cp + 4) = o1;
        }
    }
}

__global__ void __launch_bounds__(256, 2) gemm_qkv_kernel(
    const float* __restrict__ X, int M,
    const float* __restrict__ Wq, const float* __restrict__ bq,
    const float* __restrict__ Wk, const float* __restrict__ bk,
    const float* __restrict__ Wv, const float* __restrict__ bv)
{
    const float* W; const float* B; float* C;
    int z = blockIdx.z;
    if (z == 0)      { W = Wq; B = bq; C = g_q; }
    else if (z == 1) { W = Wk; B = bk; C = g_k; }
    else             { W = Wv; B = bv; C = g_v; }
    gemm_tile(X, M, W, B, C, blockIdx.y * BM, blockIdx.x * BN);
}

__global__ void __launch_bounds__(256, 2) gemm_out_kernel(
    int M, const float* __restrict__ Wo, const float* __restrict__ bo,
    float* __restrict__ out)
{
    gemm_tile(g_acc, M, Wo, bo, out, blockIdx.y * BM, blockIdx.x * BN);
}

// ---------------------------------------------------------------------------
// Edge kernel: one warp per edge (unchanged — revisit after GEMM is fixed).
// ---------------------------------------------------------------------------
__device__ __forceinline__ void red_add_v4(float* addr, float4 v) {
    asm volatile("red.global.add.v4.f32 [%0], {%1, %2, %3, %4};"
                 :: "l"(addr), "f"(v.x), "f"(v.y), "f"(v.z), "f"(v.w)
                 : "memory");
}

__global__ void __launch_bounds__(256) edge_kernel(
    const int* __restrict__ src, const int* __restrict__ dst, int E)
{
    int e = (blockIdx.x << 3) + (threadIdx.x >> 5);
    if (e >= E) return;
    int lane = threadIdx.x & 31;

    int s = src[e];
    int d = dst[e];

    const float4* qp = reinterpret_cast<const float4*>(g_q + (size_t)s * DIMC);
    const float4* kp = reinterpret_cast<const float4*>(g_k + (size_t)d * DIMC);

    float4 a0 = qp[lane];
    float4 a1 = qp[lane + 32];
    float4 b0 = kp[lane];
    float4 b1 = kp[lane + 32];

    float p0 = a0.x * b0.x + a0.y * b0.y + a0.z * b0.z + a0.w * b0.w;
    float p1 = a1.x * b1.x + a1.y * b1.y + a1.z * b1.z + a1.w * b1.w;

#pragma unroll
    for (int m = 1; m <= 4; m <<= 1) {
        p0 += __shfl_xor_sync(0xffffffffu, p0, m);
        p1 += __shfl_xor_sync(0xffffffffu, p1, m);
    }

    const float scale = 0.17677669529663687f;   // 1/sqrt(32)
    float sc0 = p0 * scale;
    float sc1 = p1 * scale;

    float sh[8];
#pragma unroll
    for (int h = 0; h < 4; h++) {
        sh[h]     = __shfl_sync(0xffffffffu, sc0, h << 3);
        sh[h + 4] = __shfl_sync(0xffffffffu, sc1, h << 3);
    }

    float mx = sh[0];
#pragma unroll
    for (int h = 1; h < 8; h++) mx = fmaxf(mx, sh[h]);
    float sum = 0.f;
#pragma unroll
    for (int h = 0; h < 8; h++) sum += expf(sh[h] - mx);
    float inv = 1.0f / sum;

    float w0 = expf(sc0 - mx) * inv;
    float w1 = expf(sc1 - mx) * inv;

    const float4* vp = reinterpret_cast<const float4*>(g_v + (size_t)s * DIMC);
    float4 v0 = vp[lane];
    float4 v1 = vp[lane + 32];

    float* op = g_acc + (size_t)d * DIMC;
    red_add_v4(op + (lane << 2),
               make_float4(v0.x * w0, v0.y * w0, v0.z * w0, v0.w * w0));
    red_add_v4(op + ((lane + 32) << 2),
               make_float4(v1.x * w1, v1.y * w1, v1.z * w1, v1.w * w1));
}

// ---------------------------------------------------------------------------
// Launch
// ---------------------------------------------------------------------------
extern "C" void kernel_launch(void* const* d_in, const int* in_sizes, int n_in,
                              void* d_out, int out_size)
{
    const float* x   = (const float*)d_in[0];
    const int*   src = (const int*)  d_in[1];
    const int*   dst = (const int*)  d_in[2];
    const float* Wq  = (const float*)d_in[3];
    const float* bq  = (const float*)d_in[4];
    const float* Wk  = (const float*)d_in[5];
    const float* bk  = (const float*)d_in[6];
    const float* Wv  = (const float*)d_in[7];
    const float* bv  = (const float*)d_in[8];
    const float* Wo  = (const float*)d_in[9];
    const float* bo  = (const float*)d_in[10];
    float* out = (float*)d_out;

    int N = in_sizes[0] / DIMC;
    int E = in_sizes[1];

    int mtiles = (N + BM - 1) / BM;

    // 1) zero accumulator
    int n4 = (N * DIMC) / 4;
    zero_acc_kernel<<<(n4 + 255) / 256, 256>>>(n4);

    // 2) Q/K/V projections
    {
        dim3 grid(DIMC / BN, mtiles, 3);
        gemm_qkv_kernel<<<grid, 256>>>(x, N, Wq, bq, Wk, bk, Wv, bv);
    }

    // 3) per-edge attention + scatter
    edge_kernel<<<(E + 7) / 8, 256>>>(src, dst, E);

    // 4) output projection
    {
        dim3 grid(DIMC / BN, mtiles, 1);
        gemm_out_kernel<<<grid, 256>>>(N, Wo, bo, out);
    }
}